// round 13
// baseline (speedup 1.0000x reference)
#include <cuda_runtime.h>
#include <math.h>
#include <stdint.h>

#define NQ    12
#define TT    8
#define BB    32
#define SHOTS 256
#define KMAX  80
#define KP    (KMAX + 1)
#define DIM   4096

typedef unsigned long long u64;

// Evolved states exp(-i t H)|init>, one complex vector per t, plus sync flags.
__device__ float2 g_states[TT][DIM];
__device__ int    g_flag[TT];   // counts ranks published (0..4); self-cleaning
__device__ int    g_cnt[TT];    // consumer count for self-clean

__device__ __forceinline__ int ld_acquire(const int* p) {
    int v;
    asm volatile("ld.acquire.gpu.s32 %0, [%1];" : "=r"(v) : "l"(p) : "memory");
    return v;
}
__device__ __forceinline__ uint32_t smem_u32(const void* p) {
    uint32_t a;
    asm("{ .reg .u64 t; cvta.to.shared.u64 t, %1; cvt.u32.u64 %0, t; }"
        : "=r"(a) : "l"(p));
    return a;
}
__device__ __forceinline__ uint32_t mapa32(uint32_t a, uint32_t r) {
    uint32_t d;
    asm("mapa.shared::cluster.u32 %0, %1, %2;" : "=r"(d) : "r"(a), "r"(r));
    return d;
}
__device__ __forceinline__ void mbar_wait(uint32_t bar, uint32_t parity) {
    asm volatile(
        "{\n\t.reg .pred P;\n\t"
        "WL_%=:\n\t"
        "mbarrier.try_wait.parity.acquire.cta.shared::cta.b64 P, [%0], %1, 0x989680;\n\t"
        "@P bra.uni WD_%=;\n\t"
        "bra.uni WL_%=;\n\t"
        "WD_%=:\n\t}"
        :: "r"(bar), "r"(parity) : "memory");
}
__device__ __forceinline__ void mbar_expect(uint32_t bar, uint32_t bytes) {
    asm volatile("mbarrier.arrive.expect_tx.shared.b64 _, [%0], %1;"
                 :: "r"(bar), "r"(bytes) : "memory");
}
__device__ __forceinline__ void bulk_s2s(uint32_t dst, uint32_t src,
                                         uint32_t bytes, uint32_t rbar) {
    asm volatile(
        "cp.async.bulk.shared::cluster.shared::cta.mbarrier::complete_tx::bytes "
        "[%0], [%1], %2, [%3];"
        :: "r"(dst), "r"(src), "r"(bytes), "r"(rbar) : "memory");
}

// ---- packed f32x2 helpers ----
__device__ __forceinline__ u64 pk2(float lo, float hi) {
    u64 r; asm("mov.b64 %0, {%1,%2};" : "=l"(r) : "f"(lo), "f"(hi)); return r;
}
__device__ __forceinline__ void upk2(u64 v, float& lo, float& hi) {
    asm("mov.b64 {%0,%1}, %2;" : "=f"(lo), "=f"(hi) : "l"(v));
}
__device__ __forceinline__ u64 swap2(u64 v) {
    float lo, hi; upk2(v, lo, hi); return pk2(hi, lo);
}
__device__ __forceinline__ u64 fma2_(u64 a, u64 b, u64 c) {
    u64 d; asm("fma.rn.f32x2 %0, %1, %2, %3;" : "=l"(d) : "l"(a), "l"(b), "l"(c));
    return d;
}
__device__ __forceinline__ u64 mul2_(u64 a, u64 b) {
    u64 d; asm("mul.rn.f32x2 %0, %1, %2;" : "=l"(d) : "l"(a), "l"(b)); return d;
}

// ---------------------------------------------------------------------------
// One Chebyshev term, SINGLE shared recurrence, 4-CTA cluster.
// CTA owns 1024 entries: local s = (tid<<1)|c packed in one u64/thread.
// Global s = (rank<<10)|local. Taps: bit0 = in-u64 swap (regs);
// bits1..9 = own smem LDS.64; bit10 = mirror A (peer rank^1);
// bit11 = mirror B (peer rank^2), both read after the stage-barrier wait.
// All 8 ts accumulate from the same iterate with per-t coefficients
// (smem broadcast loads, zero-padded past each t's K_t).
// ---------------------------------------------------------------------------
template<bool EVEN>
__device__ __forceinline__ void cheb_term(
    u64& cur2, u64& prevn2, u64 (&psr2)[TT], u64 (&psi2)[TT],
    u64 diag2, const u64 (&pxp)[12],
    const u64* __restrict__ SRC, u64* __restrict__ DST,
    const u64* __restrict__ MIRA, const u64* __restrict__ MIRB,
    uint32_t bar_in, int& ph_in, bool do_wait,
    uint32_t dstA, uint32_t dstB, uint32_t src_addr,
    uint32_t rbarA, uint32_t rbarB, bool do_send,
    const int (&tapx)[9], int tid, const float* __restrict__ cf /* s_c? + k */)
{
    u64 a = mul2_(diag2, cur2);
    a = fma2_(pxp[0], swap2(cur2), a);
    // bits 1..9: own-quarter smem taps (conflict-free LDS.64)
#pragma unroll
    for (int b = 0; b < 9; b++)
        a = fma2_(pxp[1 + b], SRC[tapx[b]], a);
    // wait for peer mirrors (2 x 4KB, sent last term; usually complete)
    if (do_wait) {
        mbar_wait(bar_in, (uint32_t)ph_in);
        ph_in ^= 1;
        if (tid == 0) mbar_expect(bar_in, 8192u);
    }
    a = fma2_(pxp[10], MIRA[tid], a);
    a = fma2_(pxp[11], MIRB[tid], a);

    const u64 TWO2 = pk2(2.f, 2.f);
    const u64 M12  = pk2(-1.f, -1.f);
    const u64 nx = fma2_(TWO2, a, prevn2);   // 2*acc - prev
    DST[tid] = nx;
    prevn2 = mul2_(cur2, M12);
    cur2 = nx;
    // accumulate all 8 ts (coefficients are smem broadcasts; zero past K_t)
#pragma unroll
    for (int t8 = 0; t8 < TT; t8++) {
        const float c = cf[t8 * KP];
        const u64 C2 = pk2(c, c);
        if (EVEN) psr2[t8] = fma2_(C2, nx, psr2[t8]);
        else      psi2[t8] = fma2_(C2, nx, psi2[t8]);
    }
    __syncthreads();   // all DST stores visible CTA-wide
    if (do_send) {
        if (tid == 0) {
            asm volatile("fence.proxy.async.shared::cta;" ::: "memory");
            bulk_s2s(dstA, src_addr, 4096u, rbarA);
        }
        if (tid == 32) {
            asm volatile("fence.proxy.async.shared::cta;" ::: "memory");
            bulk_s2s(dstB, src_addr, 4096u, rbarB);
        }
    }
}

// ---------------------------------------------------------------------------
// radix-2 gate on a complex pair (X basis p=0, Y basis p=1), no scaling
// ---------------------------------------------------------------------------
__device__ __forceinline__ void gate2(int p, float& r0, float& i0,
                                      float& r1, float& i1)
{
    const float a = r0, bb = i0, c = r1, d = i1;
    if (p == 0) { r0 = a + c; i0 = bb + d; r1 = a - c; i1 = bb - d; }
    else        { r0 = a + d; i0 = bb - c; r1 = a - d; i1 = bb + c; }
}

// ---------------------------------------------------------------------------
// Fused persistent kernel. 256 CTAs x 512 threads, cluster size 4.
//   bid 0..3  : the single evolve cluster (rank = bid). One shared Chebyshev
//               recurrence; each t published (staggered) at k = K_t.
//   all bids  : measure task t = bid>>5, b = bid&31 (evolve CTAs take t0,b0-3).
// ---------------------------------------------------------------------------
__global__ void __cluster_dims__(4, 1, 1) __launch_bounds__(512, 1)
fused_kernel(const int* __restrict__ d_init,
             const float* __restrict__ d_ts,
             const int* __restrict__ d_pauli,
             const int* __restrict__ d_idx,
             const float* __restrict__ d_px,
             const float* __restrict__ d_pzz,
             float* __restrict__ d_out)
{
    // pool (32KB): buf0|buf1|mirA0|mirA1|mirB0|mirB1 (4KB each) + coeffs.
    // measure reuses [0, DIM) = re, [DIM, 2*DIM) = im.
    __shared__ __align__(16) float pool[2 * DIM];
    __shared__ __align__(8) unsigned long long s_bar[2];
    __shared__ int s_pub[KP];        // per-k publication bitmask over ts
    __shared__ int s_Karr[9];        // K_t per t; [8] = K_max
    __shared__ int s_misc[3 * NQ + 2];

    const int tid = threadIdx.x;
    const int bid = blockIdx.x;
    const int t = bid >> 5;
    const int b = bid & 31;

    if (bid < 4) {
        // ================= EVOLVE (shared recurrence, rank = bid) ==========
        u64* pairs = reinterpret_cast<u64*>(pool);
        u64* buf0  = pairs;              // gen-even (512 u64 = 4KB)
        u64* buf1  = pairs + 512;        // gen-odd
        u64* mirA0 = pairs + 1024;       // peer rank^1, gen-even
        u64* mirA1 = pairs + 1536;
        u64* mirB0 = pairs + 2048;       // peer rank^2, gen-even
        u64* mirB1 = pairs + 2560;
        float* s_cr = pool + 6144;       // [TT][KP]
        float* s_ci = s_cr + TT * KP;

        uint32_t rank;
        asm("mov.u32 %0, %%cluster_ctarank;" : "=r"(rank));
        const uint32_t pA = rank ^ 1u;
        const uint32_t pB = rank ^ 2u;

        float px[NQ];
        float lambda = 0.f;
#pragma unroll
        for (int i = 0; i < NQ; i++) { px[i] = d_px[i]; lambda += fabsf(px[i]); }
        float pzz[NQ - 1];
#pragma unroll
        for (int i = 0; i < NQ - 1; i++) { pzz[i] = d_pzz[i]; lambda += fabsf(pzz[i]); }
        if (lambda < 1e-20f) lambda = 1e-20f;
        const float inv_l = 1.0f / lambda;
#pragma unroll
        for (int i = 0; i < NQ; i++) px[i] *= inv_l;

        u64 pxp[12];
#pragma unroll
        for (int i = 0; i < NQ; i++) pxp[i] = pk2(px[i], px[i]);

        // scaled diagonal for owned entries: s = (rank<<10)|(tid<<1)|c
        float diag[2];
#pragma unroll
        for (int c = 0; c < 2; c++) {
            const int s = ((int)rank << 10) | (tid << 1) | c;
            float d = 0.f;
#pragma unroll
            for (int i = 0; i < NQ - 1; i++) {
                const int bi = (s >> i) & 1;
                const int bj = (s >> (i + 1)) & 1;
                d += (bi == bj) ? pzz[i] : -pzz[i];
            }
            diag[c] = d * inv_l;
        }
        const u64 diag2 = pk2(diag[0], diag[1]);

        // zero publication mask, then threads 0..7 each run one Miller
        for (int i = tid; i < KP; i += 512) s_pub[i] = 0;
        if (tid == 0) {
            const uint32_t b0 = smem_u32(&s_bar[0]);
            const uint32_t b1 = smem_u32(&s_bar[1]);
            asm volatile("mbarrier.init.shared.b64 [%0], 1;" :: "r"(b0) : "memory");
            asm volatile("mbarrier.init.shared.b64 [%0], 1;" :: "r"(b1) : "memory");
            mbar_expect(b0, 8192u);      // phase 0, stage 0 (even gens)
            mbar_expect(b1, 8192u);      // phase 0, stage 1 (odd gens)
        }
        __syncthreads();

        if (tid < TT) {
            double x = (double)d_ts[tid] * (double)lambda;
            if (x < 1e-5) x = 1e-5;
            int K = (int)ceil(x) + 16;
            if (K > KMAX) K = KMAX;
            if (K < 2)    K = 2;
            const int M = K + 14;
            double v[KMAX + 16];
            v[M] = 1e-30;
            const double inv_x = 1.0 / x;
            double up = 0.0;
            for (int k = M; k >= 1; k--) {
                const double nv = (2.0 * (double)k * inv_x) * v[k] - up;
                up = v[k];
                v[k - 1] = nv;
            }
            double S = v[0];
            for (int m = 2; m <= M; m += 2) S += 2.0 * v[m];
            const double invS = 1.0 / S;
            while (K > 2 && fabs(v[K] * invS) < 4e-4) K--;   // adaptive trim
            float* cr = s_cr + tid * KP;
            float* ci = s_ci + tid * KP;
            for (int k = 0; k <= K; k++) {
                const double Jk = v[k] * invS;
                const double c  = (k == 0) ? Jk : 2.0 * Jk;
                float crv = 0.f, civ = 0.f;
                switch (k & 3) {         // (-i)^k
                    case 0: crv = (float)c;  break;
                    case 1: civ = (float)-c; break;
                    case 2: crv = (float)-c; break;
                    case 3: civ = (float)c;  break;
                }
                cr[k] = crv;
                ci[k] = civ;
            }
            for (int k = K + 1; k <= KMAX; k++) { cr[k] = 0.f; ci[k] = 0.f; }
            s_Karr[tid] = K;
            atomicOr(&s_pub[K], 1 << tid);
        }
        __syncthreads();
        if (tid == 0) {
            int km = 2;
            for (int i = 0; i < TT; i++) if (s_Karr[i] > km) km = s_Karr[i];
            s_Karr[8] = km;
        }
        __syncthreads();

        const int Kmax = s_Karr[8];
        const int init = *d_init;

        // tap pair-indices and remote addresses
        int tapx[9];
#pragma unroll
        for (int b2 = 0; b2 < 9; b2++) tapx[b2] = tid ^ (1 << b2);
        const uint32_t pbase = smem_u32(pool);
        const uint32_t bar0 = smem_u32(&s_bar[0]);
        const uint32_t bar1 = smem_u32(&s_bar[1]);
        // even-gen sends: my buf0 -> pA's mirA0, pB's mirB0 (their stage-0 bar)
        const uint32_t dA0 = mapa32(pbase + 8192u,  pA);
        const uint32_t dB0 = mapa32(pbase + 16384u, pB);
        const uint32_t rbA0 = mapa32(bar0, pA);
        const uint32_t rbB0 = mapa32(bar0, pB);
        // odd-gen sends: my buf1 -> pA's mirA1, pB's mirB1 (their stage-1 bar)
        const uint32_t dA1 = mapa32(pbase + 12288u, pA);
        const uint32_t dB1 = mapa32(pbase + 20480u, pB);
        const uint32_t rbA1 = mapa32(bar1, pA);
        const uint32_t rbB1 = mapa32(bar1, pB);

        // phi_0 = e_init ; phi_1 = H' e_init (analytic) for own quarter and
        // both peers' quarters (mirror seeds).
        u64 cur2, prevn2, psr2[TT], psi2[TT];
        {
            float p0v[2], p1v[2], qa[2], qb[2];
#pragma unroll
            for (int c = 0; c < 2; c++) {
                const int so = ((int)rank << 10) | (tid << 1) | c;
                const int sa = ((int)pA   << 10) | (tid << 1) | c;
                const int sb = ((int)pB   << 10) | (tid << 1) | c;
                p0v[c] = (so == init) ? 1.f : 0.f;
                float p1 = (so == init) ? diag[c] : 0.f;
                int d = so ^ init;
#pragma unroll
                for (int i = 0; i < NQ; i++)
                    if (d == (1 << i)) p1 = px[i];
                p1v[c] = p1;
                // peer A's phi1 entry
                float q = 0.f;
                if (sa == init) {
                    float dd = 0.f;
#pragma unroll
                    for (int i = 0; i < NQ - 1; i++) {
                        const int bi = (sa >> i) & 1, bj = (sa >> (i + 1)) & 1;
                        dd += (bi == bj) ? pzz[i] : -pzz[i];
                    }
                    q = dd * inv_l;
                }
                d = sa ^ init;
#pragma unroll
                for (int i = 0; i < NQ; i++)
                    if (d == (1 << i)) q = px[i];
                qa[c] = q;
                // peer B's phi1 entry
                q = 0.f;
                if (sb == init) {
                    float dd = 0.f;
#pragma unroll
                    for (int i = 0; i < NQ - 1; i++) {
                        const int bi = (sb >> i) & 1, bj = (sb >> (i + 1)) & 1;
                        dd += (bi == bj) ? pzz[i] : -pzz[i];
                    }
                    q = dd * inv_l;
                }
                d = sb ^ init;
#pragma unroll
                for (int i = 0; i < NQ; i++)
                    if (d == (1 << i)) q = px[i];
                qb[c] = q;
            }
            cur2   = pk2(p1v[0], p1v[1]);
            prevn2 = pk2(-p0v[0], -p0v[1]);
#pragma unroll
            for (int t8 = 0; t8 < TT; t8++) {
                const float cr0 = s_cr[t8 * KP];       // broadcast
                const float ci1 = s_ci[t8 * KP + 1];
                psr2[t8] = pk2(cr0 * p0v[0], cr0 * p0v[1]);
                psi2[t8] = pk2(ci1 * p1v[0], ci1 * p1v[1]);
            }
            buf1[tid]  = cur2;                  // phi_1 (odd gen)
            mirA1[tid] = pk2(qa[0], qa[1]);     // peer A phi_1 (analytic)
            mirB1[tid] = pk2(qb[0], qb[1]);     // peer B phi_1
        }
        __syncthreads();
        asm volatile("barrier.cluster.arrive.aligned;" ::: "memory");
        asm volatile("barrier.cluster.wait.aligned;"   ::: "memory");

        int ph0 = 0, ph1 = 0;
        for (int k = 2; k <= Kmax; k++) {
            if (!(k & 1))
                cheb_term<true>(cur2, prevn2, psr2, psi2, diag2, pxp,
                                buf1, buf0, mirA1, mirB1,
                                bar1, ph1, (k > 2),
                                dA0, dB0, pbase, rbA0, rbB0, (k < Kmax),
                                tapx, tid, s_cr + k);
            else
                cheb_term<false>(cur2, prevn2, psr2, psi2, diag2, pxp,
                                 buf0, buf1, mirA0, mirB0,
                                 bar0, ph0, true,
                                 dA1, dB1, pbase + 4096u, rbA1, rbB1, (k < Kmax),
                                 tapx, tid, s_ci + k);
            // staggered publication: ts whose series ends at this k
            const int pub = s_pub[k];
            if (pub) {
#pragma unroll
                for (int t8 = 0; t8 < TT; t8++) {
                    if (pub & (1 << t8)) {
                        float r0, r1, i0, i1;
                        upk2(psr2[t8], r0, r1);
                        upk2(psi2[t8], i0, i1);
                        const int s = ((int)rank << 10) | (tid << 1);
                        g_states[t8][s]     = make_float2(r0, i0);
                        g_states[t8][s | 1] = make_float2(r1, i1);
                    }
                }
                __syncthreads();
                if (tid == 0) {
                    __threadfence();
#pragma unroll
                    for (int t8 = 0; t8 < TT; t8++)
                        if (pub & (1 << t8)) atomicAdd(&g_flag[t8], 1);
                }
            }
        }
        // keep cluster alive until all ranks stop touching peer smem
        asm volatile("barrier.cluster.arrive.aligned;" ::: "memory");
        asm volatile("barrier.cluster.wait.aligned;"   ::: "memory");
    }

    // ================= WAIT for all 4 quarters of t =================
    if (tid == 0) {
        while (ld_acquire(&g_flag[t]) < 4) __nanosleep(64);
        const int n = atomicAdd(&g_cnt[t], 1);
        if (n == 31) {               // last of 32 consumers: self-clean
            g_cnt[t]  = 0;
            g_flag[t] = 0;
        }
    }
    __syncthreads();

    // ================= MEASURE (t, b) =================
    {
        float* re = pool;
        float* im = pool + DIM;
        int* p_raw = s_misc;
        int* nzm   = s_misc + NQ;
        int* nzp   = s_misc + 2 * NQ;
        int* s_nnz = s_misc + 3 * NQ;

        if (tid < NQ) p_raw[tid] = d_pauli[b * NQ + tid];

#pragma unroll
        for (int r = 0; r < DIM / 512; r++) {
            const int s = tid + (r << 9);
            const float2 v = __ldcg(&g_states[t][s]);
            re[s] = v.x;
            im[s] = v.y;
        }
        __syncthreads();

        if (tid == 0) {
            int c = 0;
            for (int m = NQ - 1; m >= 0; m--) {
                const int p = p_raw[NQ - 1 - m];
                if (p != 2) { nzm[c] = m; nzp[c] = p; c++; }
            }
            *s_nnz = c;
        }
        __syncthreads();

        const int nnz = *s_nnz;
        int i = 0;
        // radix-8: three non-Z qubits per sweep (mh > mm > ml; list descending)
        for (; i + 2 < nnz; i += 3) {
            const int mh = nzm[i], mm = nzm[i + 1], ml = nzm[i + 2];
            const int ph_ = nzp[i], pm_ = nzp[i + 1], pl_ = nzp[i + 2];
            const int lml = (1 << ml) - 1;
            const int lmm = (1 << mm) - 1;
            const int lmh = (1 << mh) - 1;
            const int ol = 1 << ml, om = 1 << mm, oh = 1 << mh;
            int x = ((tid & ~lml) << 1) | (tid & lml);
            x = ((x & ~lmm) << 1) | (x & lmm);
            const int s0 = ((x & ~lmh) << 1) | (x & lmh);
            int sidx[8];
#pragma unroll
            for (int j = 0; j < 8; j++)
                sidx[j] = s0 | ((j & 1) ? ol : 0) | ((j & 2) ? om : 0) | ((j & 4) ? oh : 0);
            float rr[8], ii[8];
#pragma unroll
            for (int j = 0; j < 8; j++) { rr[j] = re[sidx[j]]; ii[j] = im[sidx[j]]; }
#pragma unroll
            for (int j = 0; j < 8; j += 2)
                gate2(pl_, rr[j], ii[j], rr[j + 1], ii[j + 1]);
#pragma unroll
            for (int j = 0; j < 2; j++) {
                gate2(pm_, rr[j], ii[j], rr[j + 2], ii[j + 2]);
                gate2(pm_, rr[j + 4], ii[j + 4], rr[j + 6], ii[j + 6]);
            }
#pragma unroll
            for (int j = 0; j < 4; j++)
                gate2(ph_, rr[j], ii[j], rr[j + 4], ii[j + 4]);
            const float sc = 0.35355339059327376f;   // (1/sqrt2)^3
#pragma unroll
            for (int j = 0; j < 8; j++) {
                re[sidx[j]] = rr[j] * sc;
                im[sidx[j]] = ii[j] * sc;
            }
            __syncthreads();
        }
        // leftover: two non-Z qubits (radix-4)
        if (i + 1 < nnz) {
            const int mh = nzm[i], ml = nzm[i + 1];
            const int ph_ = nzp[i], pl_ = nzp[i + 1];
            const int lml = (1 << ml) - 1;
            const int lmh = (1 << mh) - 1;
            const int ol = 1 << ml, oh = 1 << mh;
#pragma unroll
            for (int r = 0; r < 2; r++) {
                const int g = tid + (r << 9);
                const int x = ((g & ~lml) << 1) | (g & lml);
                const int s00 = ((x & ~lmh) << 1) | (x & lmh);
                float rr[4], ii[4];
                const int sidx[4] = { s00, s00 | ol, s00 | oh, s00 | oh | ol };
#pragma unroll
                for (int j = 0; j < 4; j++) { rr[j] = re[sidx[j]]; ii[j] = im[sidx[j]]; }
                gate2(pl_, rr[0], ii[0], rr[1], ii[1]);
                gate2(pl_, rr[2], ii[2], rr[3], ii[3]);
                gate2(ph_, rr[0], ii[0], rr[2], ii[2]);
                gate2(ph_, rr[1], ii[1], rr[3], ii[3]);
#pragma unroll
                for (int j = 0; j < 4; j++) {
                    re[sidx[j]] = rr[j] * 0.5f;
                    im[sidx[j]] = ii[j] * 0.5f;
                }
            }
            i += 2;
            __syncthreads();
        }
        // leftover: single non-Z qubit (radix-2)
        if (i < nnz) {
            const int m = nzm[i], p = nzp[i];
            const int lm = (1 << m) - 1;
            const float s2 = 0.70710678118654752f;
#pragma unroll
            for (int r = 0; r < 4; r++) {
                const int q  = tid + (r << 9);
                const int sA = ((q & ~lm) << 1) | (q & lm);
                const int sB = sA | (1 << m);
                float r0 = re[sA], i0 = im[sA];
                float r1 = re[sB], i1 = im[sB];
                gate2(p, r0, i0, r1, i1);
                re[sA] = r0 * s2; im[sA] = i0 * s2;
                re[sB] = r1 * s2; im[sB] = i1 * s2;
            }
            __syncthreads();
        }

        if (tid < SHOTS) {
            const int base2 = (t * BB + b) * SHOTS;
            const int idx   = d_idx[base2 + tid];
            const float pr  = re[idx];
            const float pi  = im[idx];
            d_out[base2 + tid] = pr * pr + pi * pi;
        }
    }
}

// ---------------------------------------------------------------------------
extern "C" void kernel_launch(void* const* d_in, const int* in_sizes, int n_in,
                              void* d_out, int out_size)
{
    const int*   d_init  = (const int*)  d_in[0];
    const float* d_ts    = (const float*)d_in[1];
    const int*   d_pauli = (const int*)  d_in[2];
    const int*   d_idx   = (const int*)  d_in[3];
    const float* d_px    = (const float*)d_in[4];
    const float* d_pzz   = (const float*)d_in[5];

    fused_kernel<<<TT * BB, 512>>>(d_init, d_ts, d_pauli, d_idx,
                                   d_px, d_pzz, (float*)d_out);
}